// round 10
// baseline (speedup 1.0000x reference)
#include <cuda_runtime.h>

#define BB 256
#define TT 512
#define EMBD 64
#define HID 128

__device__ float g_pre1[(long)TT * BB * HID];   // [t][b][j], 64 MB
__device__ float g_h2[BB * HID];

// tanh(x) = 1 - 2/(e^{2x}+1) via MUFU. |err| ~1e-7 per call.
__device__ __forceinline__ float fast_tanh(float x) {
    float xc = fminf(fmaxf(x, -20.f), 20.f);
    float e;
    asm("ex2.approx.f32 %0, %1;" : "=f"(e) : "f"(xc * 2.8853900817779268f));
    float r;
    asm("rcp.approx.f32 %0, %1;" : "=f"(r) : "f"(e + 1.f));
    return fmaf(-2.f, r, 1.f);
}

// ---------------------------------------------------------------------------
// Kernel 1: pre1[t][b][j] = dot(emb[x[b,t]], Wih1[j]) + b_ih1[j] + b_hh1[j]
// (proven R1 version, byte-identical)
// ---------------------------------------------------------------------------
__global__ __launch_bounds__(128) void k_pre1(
    const int* __restrict__ x, const float* __restrict__ emb,
    const float* __restrict__ Wih1, const float* __restrict__ bih1,
    const float* __restrict__ bhh1)
{
    __shared__ __align__(16) float shW[HID * 68];
    __shared__ __align__(16) float4 shE[8 * 16];
    __shared__ int shX[8];

    const int tid = threadIdx.x;

    for (int it = 0; it < 64; ++it) {
        int f = it * 128 + tid;
        int j = f >> 6, k = f & 63;
        shW[j * 68 + k] = Wih1[f];
    }
    __syncthreads();

    float Wr[64];
#pragma unroll
    for (int i = 0; i < 64; ++i) Wr[i] = shW[tid * 68 + i];
    const float bb = bih1[tid] + bhh1[tid];

    const int base = blockIdx.x * 256;
    const float4* __restrict__ e4 = (const float4*)emb;

    for (int it = 0; it < 32; ++it) {
        const int rid0 = base + it * 8;             // rid = t*256 + b
        if (tid < 8) {
            int rid = rid0 + tid;
            int t = rid >> 8, b = rid & 255;
            shX[tid] = x[b * TT + t];
        }
        __syncthreads();
        {
            int r = tid >> 4, f = tid & 15;
            shE[r * 16 + f] = e4[(long)shX[r] * 16 + f];
        }
        __syncthreads();

        float acc[8];
#pragma unroll
        for (int r = 0; r < 8; ++r) acc[r] = bb;
#pragma unroll
        for (int k4 = 0; k4 < 16; ++k4) {
#pragma unroll
            for (int r = 0; r < 8; ++r) {
                float4 e = shE[r * 16 + k4];
                acc[r] = fmaf(Wr[4 * k4 + 0], e.x, acc[r]);
                acc[r] = fmaf(Wr[4 * k4 + 1], e.y, acc[r]);
                acc[r] = fmaf(Wr[4 * k4 + 2], e.z, acc[r]);
                acc[r] = fmaf(Wr[4 * k4 + 3], e.w, acc[r]);
            }
        }
#pragma unroll
        for (int r = 0; r < 8; ++r)
            g_pre1[(long)(rid0 + r) * HID + tid] = acc[r];
        __syncthreads();
    }
}

// ---------------------------------------------------------------------------
// Kernel 2: fused two-layer scan with matrix-split warp roles.
// 128 blocks x 256 threads; block handles rows b0, b0+1.
//   p0 (tid<128): Wfull = full W_hh1 row j, Whalf = W_ih2 row j, k in [0,64)
//   p1 (tid>=128): Wfull = full W_hh2 row j, Whalf = W_ih2 row j, k in [64,128)
// Per step:
//   A: both roles compute full 128-deep dots (rows 0,1) with Wfull.
//      p0 finishes h1_new = tanh(pre + dot) directly (no exchange), writes smem.
//      p1 keeps its W_hh2 dots in registers.                 [BAR all]
//   B: all compute W_ih2 half-dots of h1_new; p0 publishes partials. [BAR all]
//   C: p1 combines + tanh -> h2_new -> smem; p0 prefetches pre(t+1).
//      [named barrier over p1's 128 threads only]
// ---------------------------------------------------------------------------
__global__ __launch_bounds__(256, 1) void k_scan(
    const float* __restrict__ Whh1, const float* __restrict__ Wih2,
    const float* __restrict__ Whh2, const float* __restrict__ bih2,
    const float* __restrict__ bhh2)
{
    __shared__ __align__(16) float h1s[2][2][HID];   // [buf][row][j]
    __shared__ __align__(16) float h2s[2][HID];      // [row][j]
    __shared__ __align__(16) float part[2][HID];     // p0 half-dot partials

    const int tid = threadIdx.x;
    const int j = tid & 127;
    const int p = tid >> 7;            // role (warp-uniform)
    const int b0 = blockIdx.x * 2;

    // Full recurrent row (W_hh1 for p0, W_hh2 for p1) + W_ih2 half-row.
    float Wfull[128], Whalf[64];
    {
        const float4* wf = (const float4*)((p ? Whh2 : Whh1) + j * HID);
        const float4* wh = (const float4*)(Wih2 + j * HID + p * 64);
#pragma unroll
        for (int i = 0; i < 32; ++i) {
            float4 a = wf[i];
            Wfull[4 * i] = a.x; Wfull[4 * i + 1] = a.y;
            Wfull[4 * i + 2] = a.z; Wfull[4 * i + 3] = a.w;
        }
#pragma unroll
        for (int i = 0; i < 16; ++i) {
            float4 a = wh[i];
            Whalf[4 * i] = a.x; Whalf[4 * i + 1] = a.y;
            Whalf[4 * i + 2] = a.z; Whalf[4 * i + 3] = a.w;
        }
    }
    const float bb2 = bih2[j] + bhh2[j];

    // Zero h state.
    {
        int i0 = tid;            // 256 threads cover 512 entries of h1s in 2 steps
        ((float*)h1s)[i0] = 0.f;
        ((float*)h1s)[i0 + 256] = 0.f;
        ((float*)h2s)[i0] = 0.f;
    }
    __syncthreads();

    // pre1 streams for both rows (p0 only).
    const float* preP0 = g_pre1 + (long)b0 * HID + j;
    const float* preP1 = preP0 + HID;
    float pr0 = 0.f, pr1 = 0.f;
    if (p == 0) { pr0 = preP0[0]; pr1 = preP1[0]; }

    float d0 = 0.f, d1 = 0.f;    // p1's W_hh2 dots

    for (int t = 0; t < TT; ++t) {
        const int cur = t & 1, nxt = cur ^ 1;

        // ---- Phase A: full dots with Wfull ----
        const float4* s0 = (const float4*)(p ? &h2s[0][0] : &h1s[cur][0][0]);
        const float4* s1 = (const float4*)(p ? &h2s[1][0] : &h1s[cur][1][0]);
        float a0 = 0.f, a1 = 0.f;
#pragma unroll
        for (int i = 0; i < 32; ++i) {
            float4 u = s0[i];
            a0 = fmaf(Wfull[4 * i + 0], u.x, a0);
            a0 = fmaf(Wfull[4 * i + 1], u.y, a0);
            a0 = fmaf(Wfull[4 * i + 2], u.z, a0);
            a0 = fmaf(Wfull[4 * i + 3], u.w, a0);
            float4 v = s1[i];
            a1 = fmaf(Wfull[4 * i + 0], v.x, a1);
            a1 = fmaf(Wfull[4 * i + 1], v.y, a1);
            a1 = fmaf(Wfull[4 * i + 2], v.z, a1);
            a1 = fmaf(Wfull[4 * i + 3], v.w, a1);
        }
        if (p == 0) {
            h1s[nxt][0][j] = fast_tanh(pr0 + a0);
            h1s[nxt][1][j] = fast_tanh(pr1 + a1);
        } else {
            d0 = a0; d1 = a1;
        }
        __syncthreads();                         // BAR 1: h1_new published

        // ---- Phase B: W_ih2 half-dots of h1_new ----
        const float4* n0 = (const float4*)&h1s[nxt][0][p * 64];
        const float4* n1 = (const float4*)&h1s[nxt][1][p * 64];
        float c0 = 0.f, c1 = 0.f;
#pragma unroll
        for (int i = 0; i < 16; ++i) {
            float4 u = n0[i];
            c0 = fmaf(Whalf[4 * i + 0], u.x, c0);
            c0 = fmaf(Whalf[4 * i + 1], u.y, c0);
            c0 = fmaf(Whalf[4 * i + 2], u.z, c0);
            c0 = fmaf(Whalf[4 * i + 3], u.w, c0);
            float4 v = n1[i];
            c1 = fmaf(Whalf[4 * i + 0], v.x, c1);
            c1 = fmaf(Whalf[4 * i + 1], v.y, c1);
            c1 = fmaf(Whalf[4 * i + 2], v.z, c1);
            c1 = fmaf(Whalf[4 * i + 3], v.w, c1);
        }
        if (p == 0) { part[0][j] = c0; part[1][j] = c1; }
        __syncthreads();                         // BAR 2: partials published

        // ---- Phase C ----
        if (p == 0) {
            if (t + 1 < TT) {
                pr0 = preP0[(long)(t + 1) * BB * HID];
                pr1 = preP1[(long)(t + 1) * BB * HID];
            }
        } else {
            h2s[0][j] = fast_tanh(bb2 + part[0][j] + c0 + d0);
            h2s[1][j] = fast_tanh(bb2 + part[1][j] + c1 + d1);
            asm volatile("bar.sync 1, 128;" ::: "memory");   // p1-group only
        }
    }

    if (p == 1) {
        g_h2[(b0 + 0) * HID + j] = h2s[0][j];
        g_h2[(b0 + 1) * HID + j] = h2s[1][j];
    }
}

// ---------------------------------------------------------------------------
// Kernel 3: epilogue — LN -> proj -> tanh -> LN. One block per batch row.
// ---------------------------------------------------------------------------
__global__ __launch_bounds__(128) void k_epi(
    const float* __restrict__ ln_g, const float* __restrict__ ln_b,
    const float* __restrict__ projW, const float* __restrict__ proj_b,
    const float* __restrict__ on_g, const float* __restrict__ on_b,
    float* __restrict__ out)
{
    __shared__ __align__(16) float sh_rep[HID];
    __shared__ float sh_red[8];

    const int j = threadIdx.x;
    const int b = blockIdx.x;

    float v = g_h2[b * HID + j];

    // LN 1
    float s = v, q = v * v;
#pragma unroll
    for (int o = 16; o; o >>= 1) {
        s += __shfl_xor_sync(0xffffffffu, s, o);
        q += __shfl_xor_sync(0xffffffffu, q, o);
    }
    if ((j & 31) == 0) { sh_red[j >> 5] = s; sh_red[4 + (j >> 5)] = q; }
    __syncthreads();
    s = sh_red[0] + sh_red[1] + sh_red[2] + sh_red[3];
    q = sh_red[4] + sh_red[5] + sh_red[6] + sh_red[7];
    float mu = s * (1.f / HID);
    float var = q * (1.f / HID) - mu * mu;
    float rep = (v - mu) * rsqrtf(var + 1e-5f) * ln_g[j] + ln_b[j];
    sh_rep[j] = rep;
    __syncthreads();

    // proj + tanh
    float acc = proj_b[j];
    const float4* w4 = (const float4*)(projW + j * HID);
    const float4* r4 = (const float4*)sh_rep;
#pragma unroll
    for (int i = 0; i < 32; ++i) {
        float4 w = __ldg(&w4[i]);
        float4 r = r4[i];
        acc = fmaf(w.x, r.x, acc);
        acc = fmaf(w.y, r.y, acc);
        acc = fmaf(w.z, r.z, acc);
        acc = fmaf(w.w, r.w, acc);
    }
    float tv = tanhf(acc);

    // LN 2
    __syncthreads();
    s = tv; q = tv * tv;
#pragma unroll
    for (int o = 16; o; o >>= 1) {
        s += __shfl_xor_sync(0xffffffffu, s, o);
        q += __shfl_xor_sync(0xffffffffu, q, o);
    }
    if ((j & 31) == 0) { sh_red[j >> 5] = s; sh_red[4 + (j >> 5)] = q; }
    __syncthreads();
    s = sh_red[0] + sh_red[1] + sh_red[2] + sh_red[3];
    q = sh_red[4] + sh_red[5] + sh_red[6] + sh_red[7];
    float mu2 = s * (1.f / HID);
    float var2 = q * (1.f / HID) - mu2 * mu2;
    out[b * HID + j] = (tv - mu2) * rsqrtf(var2 + 1e-5f) * on_g[j] + on_b[j];
}

// ---------------------------------------------------------------------------
extern "C" void kernel_launch(void* const* d_in, const int* in_sizes, int n_in,
                              void* d_out, int out_size)
{
    const int*   x     = (const int*)  d_in[0];
    const float* emb   = (const float*)d_in[1];
    const float* Wih1  = (const float*)d_in[2];
    const float* bih1  = (const float*)d_in[3];
    const float* Whh1  = (const float*)d_in[4];
    const float* bhh1  = (const float*)d_in[5];
    const float* Wih2  = (const float*)d_in[6];
    const float* bih2  = (const float*)d_in[7];
    const float* Whh2  = (const float*)d_in[8];
    const float* bhh2  = (const float*)d_in[9];
    const float* ln_g  = (const float*)d_in[10];
    const float* ln_b  = (const float*)d_in[11];
    const float* projW = (const float*)d_in[12];
    const float* projb = (const float*)d_in[13];
    const float* on_g  = (const float*)d_in[14];
    const float* on_b  = (const float*)d_in[15];

    k_pre1<<<512, 128>>>(x, emb, Wih1, bih1, bhh1);
    k_scan<<<128, 256>>>(Whh1, Wih2, Whh2, bih2, bhh2);
    k_epi<<<256, 128>>>(ln_g, ln_b, projW, projb, on_g, on_b, (float*)d_out);
}